// round 16
// baseline (speedup 1.0000x reference)
#include <cuda_runtime.h>
#include <cuda_bf16.h>
#include <cstdint>
#include <math.h>

// ---------------------------------------------------------------------------
// Scratch
// ---------------------------------------------------------------------------
#define NPIX 65536
// concatenated bf16 activations: [grid(64, zero-padded) | mid(1024)]
__device__ __nv_bfloat16 g_cat[NPIX * 1088];
__device__ float         g_mid [NPIX * 1024];         // fp32 residual path
__device__ float         g_h2  [NPIX * 512];
__device__ __nv_bfloat16 g_h2_bf[NPIX * 512];
__device__ __nv_bfloat16 g_wm1F[8 * 512 * 512];
__device__ __nv_bfloat16 g_wm1G[8 * 512 * 512];
__device__ __nv_bfloat16 g_wm2F[8 * 256 * 256];
__device__ __nv_bfloat16 g_wm2G[8 * 256 * 256];
__device__ __nv_bfloat16 g_w1g_bf[1024 * 64];         // w1[:, :32] zero-padded
__device__ __nv_bfloat16 g_w2cat[512 * 1088];         // [w2grid(64pad) | w2mid(1024)]
__device__ float g_conv0[768 * 8 * 8];
__device__ float g_conv1[768 * 8 * 8];
__device__ float g_pad [1792 * 100];                  // zero-padded conv input (10x10)
__device__ float g_part[4 * 768 * 64];                // conv ic-chunk partials
__device__ float g_feat[2048];
__device__ float g_bias1[1024];

// ---------------------------------------------------------------------------
// Grid features -> bf16 into g_cat cols [0,64), stride 1088
// ---------------------------------------------------------------------------
__global__ void grid_kernel(__nv_bfloat16* __restrict__ cat) {
    int idx = blockIdx.x * blockDim.x + threadIdx.x;      // n*64 + c
    int n = idx >> 6, c = idx & 63;
    float val = 0.f;
    if (c < 32) {
        int i = n >> 8, j = n & 255;
        float r = (float)(((c & 1) ? j : i) - 128) * (float)(3.14159265358979323846 / 256.0);
        float s = exp2f(0.5f * (float)(c >> 1));
        val = sinf(r * s);
    }
    cat[(size_t)n * 1088 + c] = __float2bfloat16(val);
}

// ---------------------------------------------------------------------------
// Zero-pad [C,8,8] -> [C,10,10]
// ---------------------------------------------------------------------------
__global__ void pad_kernel(const float* __restrict__ in, float* __restrict__ out, int C) {
    int idx = blockIdx.x * blockDim.x + threadIdx.x;      // c*100 + iy*10 + ix
    if (idx >= C * 100) return;
    int c = idx / 100, r = idx % 100;
    int iy = r / 10, ix = r % 10;
    float v = 0.f;
    if (iy >= 1 && iy <= 8 && ix >= 1 && ix <= 8)
        v = in[c * 64 + (iy - 1) * 8 + (ix - 1)];
    out[idx] = v;
}

// ---------------------------------------------------------------------------
// Grouped 3x3 conv, branch-free taps (input pre-padded or valid-mode).
// grid(Cout, 4 ic-chunks), 512 threads, 8-way within-block ic split.
// ---------------------------------------------------------------------------
__global__ void conv_part_kernel(const float* __restrict__ in, const float* __restrict__ w,
                                 float* __restrict__ part,
                                 int Cout, int icpg, int ocpg,
                                 int rowStride, int chStride,
                                 int Hout, int Wout) {
    int oc = blockIdx.x;
    int chunk = blockIdx.y;                 // 0..3
    int grp = oc / ocpg;
    int csz  = icpg / 4;
    int base = chunk * csz;

    extern __shared__ float sm[];
    float* sw  = sm;                        // csz*9
    float* red = sm + csz * 9;              // 8*64
    for (int i = threadIdx.x; i < csz * 9; i += blockDim.x)
        sw[i] = w[(size_t)oc * icpg * 9 + base * 9 + i];
    __syncthreads();

    int icq = threadIdx.x >> 6;             // 0..7
    int px  = threadIdx.x & 63;
    float acc = 0.f;
    if (px < Hout * Wout) {
        int oy = px / Wout, ox = px % Wout;
        const float* inb = in + (size_t)(grp * icpg + base) * chStride
                              + oy * rowStride + ox;
        for (int ic = icq; ic < csz; ic += 8) {
            const float* ip = inb + (size_t)ic * chStride;
            const float* wp = sw + ic * 9;
            #pragma unroll
            for (int ky = 0; ky < 3; ky++)
                #pragma unroll
                for (int kx = 0; kx < 3; kx++)
                    acc = fmaf(ip[ky * rowStride + kx], wp[ky * 3 + kx], acc);
        }
    }
    red[icq * 64 + px] = acc;
    __syncthreads();
    if (icq == 0 && px < Hout * Wout) {
        float v = red[px];
        #pragma unroll
        for (int q = 1; q < 8; q++) v += red[q * 64 + px];
        part[((size_t)chunk * Cout + oc) * 64 + px] = v;
    }
}

// Reduce 4 chunk partials + bias + leaky_relu -> out[oc*HW + px]
__global__ void conv_reduce_kernel(const float* __restrict__ part,
                                   const float* __restrict__ bias,
                                   float* __restrict__ out, int Cout, int HW) {
    int idx = blockIdx.x * blockDim.x + threadIdx.x;
    if (idx >= Cout * HW) return;
    int oc = idx / HW, px = idx % HW;
    float v = bias[oc];
    #pragma unroll
    for (int c = 0; c < 4; c++)
        v += part[((size_t)c * Cout + oc) * 64 + px];
    out[idx] = v > 0.f ? v : 0.01f * v;
}

__global__ void wnorm_kernel(const float* __restrict__ v, const float* __restrict__ g,
                             __nv_bfloat16* __restrict__ w, int K) {
    int row = blockIdx.x;
    const float* vr = v + (size_t)row * K;
    float s = 0.f;
    for (int k = threadIdx.x; k < K; k += blockDim.x) { float x = vr[k]; s = fmaf(x, x, s); }
    __shared__ float red[128];
    red[threadIdx.x] = s;
    __syncthreads();
    for (int o = 64; o; o >>= 1) {
        if (threadIdx.x < o) red[threadIdx.x] += red[threadIdx.x + o];
        __syncthreads();
    }
    float scale = g[row] / sqrtf(red[0]);
    for (int k = threadIdx.x; k < K; k += blockDim.x)
        w[(size_t)row * K + k] = __float2bfloat16(vr[k] * scale);
}

__global__ void conv_w1g_kernel(const float* __restrict__ w1, __nv_bfloat16* __restrict__ o) {
    int idx = blockIdx.x * blockDim.x + threadIdx.x;   // 1024*64
    int j = idx >> 6, k = idx & 63;
    o[idx] = __float2bfloat16(k < 32 ? w1[(size_t)j * 2080 + k] : 0.f);
}
__global__ void conv_w2cat_kernel(const float* __restrict__ w2, __nv_bfloat16* __restrict__ o) {
    int idx = blockIdx.x * blockDim.x + threadIdx.x;   // 512*1088
    int j = idx / 1088, r = idx % 1088;
    float v;
    if (r < 32)       v = w2[(size_t)j * 1056 + r];
    else if (r < 64)  v = 0.f;
    else              v = w2[(size_t)j * 1056 + 32 + (r - 64)];
    o[idx] = __float2bfloat16(v);
}

__global__ void bias1_kernel(const float* __restrict__ feat, const float* __restrict__ w1,
                             const float* __restrict__ b1, float* __restrict__ out) {
    int j = blockIdx.x * 8 + (threadIdx.x >> 5);
    int lane = threadIdx.x & 31;
    const float* wr = w1 + (size_t)j * 2080 + 32;
    float s = 0.f;
    for (int k = lane; k < 2048; k += 32) s = fmaf(feat[k], wr[k], s);
    #pragma unroll
    for (int o = 16; o; o >>= 1) s += __shfl_down_sync(0xffffffffu, s, o);
    if (lane == 0) out[j] = b1[j] + s;
}

// head: fp32 h2 (accuracy margin), float4 loads
__global__ void head_kernel(const float* __restrict__ h2, const float* __restrict__ w3,
                            const float* __restrict__ b3, float* __restrict__ out) {
    __shared__ float sw[1536];
    for (int i = threadIdx.x; i < 1536; i += blockDim.x) sw[i] = w3[i];
    __syncthreads();
    int n = (blockIdx.x * blockDim.x + threadIdx.x) >> 5;
    int lane = threadIdx.x & 31;
    const float* hr = h2 + (size_t)n * 512;
    float d0 = 0.f, d1 = 0.f, d2 = 0.f;
    #pragma unroll
    for (int t = lane * 4; t < 512; t += 128) {
        float4 x = *reinterpret_cast<const float4*>(hr + t);
        d0 = fmaf(x.x, sw[t],        fmaf(x.y, sw[t + 1],        fmaf(x.z, sw[t + 2],        fmaf(x.w, sw[t + 3],        d0))));
        d1 = fmaf(x.x, sw[512 + t],  fmaf(x.y, sw[512 + t + 1],  fmaf(x.z, sw[512 + t + 2],  fmaf(x.w, sw[512 + t + 3],  d1))));
        d2 = fmaf(x.x, sw[1024 + t], fmaf(x.y, sw[1024 + t + 1], fmaf(x.z, sw[1024 + t + 2], fmaf(x.w, sw[1024 + t + 3], d2))));
    }
    #pragma unroll
    for (int o = 16; o; o >>= 1) {
        d0 += __shfl_down_sync(0xffffffffu, d0, o);
        d1 += __shfl_down_sync(0xffffffffu, d1, o);
        d2 += __shfl_down_sync(0xffffffffu, d2, o);
    }
    if (lane == 0) {
        out[n]          = 1.1f / (1.f + expf(-(d0 + b3[0]))) - 0.05f;
        out[65536 + n]  = 1.1f / (1.f + expf(-(d1 + b3[1]))) - 0.05f;
        out[131072 + n] = 1.1f / (1.f + expf(-(d2 + b3[2]))) - 0.05f;
    }
}

// ---------------------------------------------------------------------------
// bf16 GEMM: mma.sync.m16n8k16 + ldmatrix + cp.async.  (mainloop FROZEN)
// 128x128 CTA tile, 4 warps (2x2), warp tile 64x64, BK=64, 3 stages (96KB),
// 128 threads, __launch_bounds__(128,2) -> 2 CTAs/SM, fragment dbuf.
// Epilogue: streaming cache hints + dead-store flags (WBF/WC).
// ---------------------------------------------------------------------------
enum { EP_LRELU_BIAS = 1, EP_RES_OUT = 3 };

#define BM 128
#define BN 128
#define BKB 64
#define STAGES 3
#define OPB (BM * BKB * 2)        // 16 KB
#define STB (2 * OPB)             // 32 KB
#define GSMEM (STAGES * STB)      // 96 KB

__device__ __forceinline__ uint32_t smem_u32(const void* p) {
    uint32_t a;
    asm("{ .reg .u64 t; cvta.to.shared.u64 t, %1; cvt.u32.u64 %0, t; }" : "=r"(a) : "l"(p));
    return a;
}
__device__ __forceinline__ void cp_async16(uint32_t sa, const __nv_bfloat16* g) {
    asm volatile("cp.async.cg.shared.global [%0], [%1], 16;" :: "r"(sa), "l"(g));
}
__device__ __forceinline__ void ldsm4(uint32_t* r, uint32_t addr) {
    asm volatile("ldmatrix.sync.aligned.m8n8.x4.shared.b16 {%0,%1,%2,%3}, [%4];"
                 : "=r"(r[0]), "=r"(r[1]), "=r"(r[2]), "=r"(r[3]) : "r"(addr));
}
__device__ __forceinline__ void mma_bf16(float* c, const uint32_t* a, const uint32_t* b) {
    asm volatile(
        "mma.sync.aligned.m16n8k16.row.col.f32.bf16.bf16.f32 "
        "{%0,%1,%2,%3}, {%4,%5,%6,%7}, {%8,%9}, {%0,%1,%2,%3};"
        : "+f"(c[0]), "+f"(c[1]), "+f"(c[2]), "+f"(c[3])
        : "r"(a[0]), "r"(a[1]), "r"(a[2]), "r"(a[3]), "r"(b[0]), "r"(b[1]));
}
__device__ __forceinline__ uint32_t pack_bf16x2(float lo, float hi) {
    uint32_t u;
    asm("cvt.rn.bf16x2.f32 %0, %1, %2;" : "=r"(u) : "f"(hi), "f"(lo));
    return u;
}
__device__ __forceinline__ float2 ldcs_f2(const float* p) {
    float2 v;
    asm volatile("ld.global.cs.v2.f32 {%0,%1}, [%2];" : "=f"(v.x), "=f"(v.y) : "l"(p));
    return v;
}
__device__ __forceinline__ void stcs_f2(float* p, float2 v) {
    asm volatile("st.global.cs.v2.f32 [%0], {%1,%2};" :: "l"(p), "f"(v.x), "f"(v.y));
}
__device__ __forceinline__ void stcs_u32(__nv_bfloat16* p, uint32_t v) {
    asm volatile("st.global.cs.b32 [%0], %1;" :: "l"(p), "r"(v));
}

template <int EP, int WBF, int WC>
__global__ __launch_bounds__(128, 2)
void gemm_bf(const __nv_bfloat16* __restrict__ A, int lda,
             const __nv_bfloat16* __restrict__ B, int ldb,
             float* __restrict__ C, int ldc,
             __nv_bfloat16* __restrict__ Cbf, int ldcbf,
             const float* __restrict__ Res, int ldres,
             const float* __restrict__ bias, int K) {
    extern __shared__ char smem[];
    uint32_t sbase = smem_u32(smem);

    int tid = threadIdx.x;
    int wid = tid >> 5, lane = tid & 31;
    int g = lane >> 2, tg = lane & 3;
    int wm = (wid >> 1) * 64;
    int wn = (wid & 1) * 64;

    long brow = blockIdx.y, bcol = blockIdx.x;
    const __nv_bfloat16* Ab = A + brow * BM * (long)lda;
    const __nv_bfloat16* Bb = B + bcol * BN * (long)ldb;
    C   += brow * BM * (long)ldc   + bcol * BN;
    if (WBF) Cbf += brow * BM * (long)ldcbf + bcol * BN;
    Res += brow * BM * (long)ldres + bcol * BN;
    const float* biasp = bias + bcol * BN;

    uint32_t aRow[4], aXor[4], bRow[4], bXor[4];
    uint32_t akb = (lane >> 4) * 16;
    uint32_t bkb = ((lane >> 3) & 1) * 16;
    #pragma unroll
    for (int s = 0; s < 4; s++) {
        uint32_t r = wm + s * 16 + (lane & 15);
        aRow[s] = r * 128;
        aXor[s] = (r & 7) << 4;
    }
    #pragma unroll
    for (int p = 0; p < 4; p++) {
        uint32_t r = wn + p * 16 + ((lane >> 4) << 3) + (lane & 7);
        bRow[p] = r * 128;
        bXor[p] = (r & 7) << 4;
    }

    float acc[4][8][4];
    #pragma unroll
    for (int s = 0; s < 4; s++)
        #pragma unroll
        for (int nt = 0; nt < 8; nt++)
            #pragma unroll
            for (int q = 0; q < 4; q++) acc[s][nt][q] = 0.f;

    int T = K / BKB;

    auto load_stage = [&](int u, int st) {
        const __nv_bfloat16* Ag = Ab + u * BKB;
        const __nv_bfloat16* Bg = Bb + u * BKB;
        uint32_t sA = sbase + st * STB;
        uint32_t sB = sA + OPB;
        #pragma unroll
        for (int j = 0; j < 8; j++) {
            int idx = tid + 128 * j;
            int r = idx >> 3, c = idx & 7;
            uint32_t sw = r * 128 + ((c * 16) ^ ((r & 7) << 4));
            cp_async16(sA + sw, Ag + (long)r * lda + c * 8);
            cp_async16(sB + sw, Bg + (long)r * ldb + c * 8);
        }
    };

    auto load_frags = [&](uint32_t sA, uint32_t sB, int kk,
                          uint32_t af[4][4], uint32_t bp[4][4]) {
        #pragma unroll
        for (int s = 0; s < 4; s++)
            ldsm4(af[s], sA + aRow[s] + (((kk * 32) + akb) ^ aXor[s]));
        #pragma unroll
        for (int p = 0; p < 4; p++)
            ldsm4(bp[p], sB + bRow[p] + (((kk * 32) + bkb) ^ bXor[p]));
    };

    #pragma unroll
    for (int p = 0; p < STAGES - 1; p++) {
        if (p < T) load_stage(p, p);
        asm volatile("cp.async.commit_group;");
    }

    uint32_t af[2][4][4], bp[2][4][4];

    for (int t = 0; t < T; t++) {
        asm volatile("cp.async.wait_group %0;" :: "n"(STAGES - 2));
        __syncthreads();
        int u = t + STAGES - 1;
        if (u < T) load_stage(u, u % STAGES);
        asm volatile("cp.async.commit_group;");

        uint32_t sA = sbase + (t % STAGES) * STB;
        uint32_t sB = sA + OPB;

        load_frags(sA, sB, 0, af[0], bp[0]);
        #pragma unroll
        for (int kk = 0; kk < 4; kk++) {
            int cur = kk & 1, nxt = cur ^ 1;
            if (kk < 3) load_frags(sA, sB, kk + 1, af[nxt], bp[nxt]);
            #pragma unroll
            for (int s = 0; s < 4; s++)
                #pragma unroll
                for (int p = 0; p < 4; p++) {
                    mma_bf16(acc[s][p * 2 + 0], af[cur][s], &bp[cur][p][0]);
                    mma_bf16(acc[s][p * 2 + 1], af[cur][s], &bp[cur][p][2]);
                }
        }
    }

    // epilogue (streaming hints: Res/C/Cbf touched once per launch)
    #pragma unroll
    for (int s = 0; s < 4; s++) {
        #pragma unroll
        for (int half = 0; half < 2; half++) {
            long row = wm + s * 16 + g + half * 8;
            #pragma unroll
            for (int nt = 0; nt < 8; nt++) {
                int col = wn + nt * 8 + tg * 2;
                float v0 = acc[s][nt][half * 2 + 0];
                float v1 = acc[s][nt][half * 2 + 1];
                if (EP == EP_LRELU_BIAS) {
                    v0 += biasp[col]; v1 += biasp[col + 1];
                    v0 = v0 > 0.f ? v0 : 0.01f * v0;
                    v1 = v1 > 0.f ? v1 : 0.01f * v1;
                } else {  // EP_RES_OUT
                    v0 += biasp[col]; v1 += biasp[col + 1];
                    v0 = v0 > 0.f ? v0 : 0.01f * v0;
                    v1 = v1 > 0.f ? v1 : 0.01f * v1;
                    float2 r = ldcs_f2(Res + row * ldres + col);
                    v0 += r.x; v1 += r.y;
                }
                if (WC) {
                    float2 o; o.x = v0; o.y = v1;
                    stcs_f2(C + row * ldc + col, o);
                }
                if (WBF)
                    stcs_u32(Cbf + row * ldcbf + col, pack_bf16x2(v0, v1));
            }
        }
    }
}

static void launch_gemm(int ep, const __nv_bfloat16* A, int lda,
                        const __nv_bfloat16* B, int ldb,
                        float* C, int ldc, __nv_bfloat16* Cbf, int ldcbf,
                        const float* Res, int ldres,
                        const float* bias, int M, int N, int K,
                        int wbf, int wc) {
    dim3 grd(N / BN, M / BM);
    if (ep == EP_LRELU_BIAS) {
        cudaFuncSetAttribute(gemm_bf<EP_LRELU_BIAS, 1, 1>, cudaFuncAttributeMaxDynamicSharedMemorySize, GSMEM);
        gemm_bf<EP_LRELU_BIAS, 1, 1><<<grd, 128, GSMEM>>>(A, lda, B, ldb, C, ldc, Cbf, ldcbf, Res, ldres, bias, K);
    } else if (wbf && wc) {
        cudaFuncSetAttribute(gemm_bf<EP_RES_OUT, 1, 1>, cudaFuncAttributeMaxDynamicSharedMemorySize, GSMEM);
        gemm_bf<EP_RES_OUT, 1, 1><<<grd, 128, GSMEM>>>(A, lda, B, ldb, C, ldc, Cbf, ldcbf, Res, ldres, bias, K);
    } else if (wbf && !wc) {
        cudaFuncSetAttribute(gemm_bf<EP_RES_OUT, 1, 0>, cudaFuncAttributeMaxDynamicSharedMemorySize, GSMEM);
        gemm_bf<EP_RES_OUT, 1, 0><<<grd, 128, GSMEM>>>(A, lda, B, ldb, C, ldc, Cbf, ldcbf, Res, ldres, bias, K);
    } else {
        cudaFuncSetAttribute(gemm_bf<EP_RES_OUT, 0, 1>, cudaFuncAttributeMaxDynamicSharedMemorySize, GSMEM);
        gemm_bf<EP_RES_OUT, 0, 1><<<grd, 128, GSMEM>>>(A, lda, B, ldb, C, ldc, Cbf, ldcbf, Res, ldres, bias, K);
    }
}

// conv helper: optional pad + split conv + reduce (R11 configuration)
static void launch_conv(const float* in, const float* w, const float* bias, float* out,
                        float* part, float* padbuf,
                        int Cin, int Cout, int Hin, int Win,
                        int Hout, int Wout, int pad, int groups) {
    int icpg = Cin / groups;
    int ocpg = Cout / groups;
    int csz  = icpg / 4;
    int smem = (csz * 9 + 512) * 4;
    const float* src = in;
    int rowStride, chStride;
    if (pad == 1) {
        pad_kernel<<<(Cin * 100 + 255) / 256, 256>>>(in, padbuf, Cin);
        src = padbuf;
        rowStride = 10; chStride = 100;
    } else {
        rowStride = Win; chStride = Hin * Win;
    }
    conv_part_kernel<<<dim3(Cout, 4), 512, smem>>>(src, w, part, Cout, icpg, ocpg,
                                                   rowStride, chStride, Hout, Wout);
    int total = Cout * Hout * Wout;
    conv_reduce_kernel<<<(total + 255) / 256, 256>>>(part, bias, out, Cout, Hout * Wout);
}

// ---------------------------------------------------------------------------
// kernel_launch
// ---------------------------------------------------------------------------
extern "C" void kernel_launch(void* const* d_in, const int* in_sizes, int n_in,
                              void* d_out, int out_size) {
    const float* feature = (const float*)d_in[0];
    const float* cw1 = (const float*)d_in[1];  const float* cb1 = (const float*)d_in[2];
    const float* cw2 = (const float*)d_in[3];  const float* cb2 = (const float*)d_in[4];
    const float* cw3 = (const float*)d_in[5];  const float* cb3 = (const float*)d_in[6];
    const float* cw4 = (const float*)d_in[7];  const float* cb4 = (const float*)d_in[8];
    const float* cw5 = (const float*)d_in[9];  const float* cb5 = (const float*)d_in[10];
    const float* w1  = (const float*)d_in[11]; const float* b1  = (const float*)d_in[12];
    const float* m1_vf = (const float*)d_in[13]; const float* m1_gf = (const float*)d_in[14];
    const float* m1_bf = (const float*)d_in[15]; const float* m1_vg = (const float*)d_in[16];
    const float* m1_gg = (const float*)d_in[17]; const float* m1_bg = (const float*)d_in[18];
    const float* w2  = (const float*)d_in[19]; const float* b2  = (const float*)d_in[20];
    const float* m2_vf = (const float*)d_in[21]; const float* m2_gf = (const float*)d_in[22];
    const float* m2_bf = (const float*)d_in[23]; const float* m2_vg = (const float*)d_in[24];
    const float* m2_gg = (const float*)d_in[25]; const float* m2_bg = (const float*)d_in[26];
    const float* w3  = (const float*)d_in[27]; const float* b3  = (const float*)d_in[28];
    float* out = (float*)d_out;

    __nv_bfloat16 *cat, *h2_bf, *wm1F, *wm1G, *wm2F, *wm2G, *w1g, *w2c;
    float *mid, *h2, *conv0, *conv1, *padb, *part, *feat, *bias1;
    cudaGetSymbolAddress((void**)&cat,   g_cat);
    cudaGetSymbolAddress((void**)&mid,   g_mid);
    cudaGetSymbolAddress((void**)&h2,    g_h2);
    cudaGetSymbolAddress((void**)&h2_bf, g_h2_bf);
    cudaGetSymbolAddress((void**)&wm1F,  g_wm1F);
    cudaGetSymbolAddress((void**)&wm1G,  g_wm1G);
    cudaGetSymbolAddress((void**)&wm2F,  g_wm2F);
    cudaGetSymbolAddress((void**)&wm2G,  g_wm2G);
    cudaGetSymbolAddress((void**)&w1g,   g_w1g_bf);
    cudaGetSymbolAddress((void**)&w2c,   g_w2cat);
    cudaGetSymbolAddress((void**)&conv0, g_conv0);
    cudaGetSymbolAddress((void**)&conv1, g_conv1);
    cudaGetSymbolAddress((void**)&padb,  g_pad);
    cudaGetSymbolAddress((void**)&part,  g_part);
    cudaGetSymbolAddress((void**)&feat,  g_feat);
    cudaGetSymbolAddress((void**)&bias1, g_bias1);

    // --- positional grid features into cat[:, 0:64] ---
    grid_kernel<<<(NPIX * 64) / 256, 256>>>(cat);

    // --- conv stack ---
    launch_conv(feature, cw1, cb1, conv0, part, padb, 1792, 768, 8, 8, 8, 8, 1, 4);
    launch_conv(conv0,   cw2, cb2, conv1, part, padb, 768,  768, 8, 8, 8, 8, 1, 3);
    launch_conv(conv1,   cw3, cb3, conv0, part, padb, 768,  768, 8, 8, 8, 8, 1, 2);
    launch_conv(conv0,   cw4, cb4, conv1, part, padb, 768,  768, 8, 8, 6, 6, 0, 3);
    launch_conv(conv1,   cw5, cb5, feat,  part, padb, 768,  128, 6, 6, 4, 4, 0, 1);

    // --- fold feat @ w1[:,32:].T + b1 into a bias vector ---
    bias1_kernel<<<128, 256>>>(feat, w1, b1, bias1);

    // --- weight prep (bf16) ---
    wnorm_kernel<<<8 * 512, 128>>>(m1_vf, m1_gf, wm1F, 512);
    wnorm_kernel<<<8 * 512, 128>>>(m1_vg, m1_gg, wm1G, 512);
    wnorm_kernel<<<8 * 256, 128>>>(m2_vf, m2_gf, wm2F, 256);
    wnorm_kernel<<<8 * 256, 128>>>(m2_vg, m2_gg, wm2G, 256);
    conv_w1g_kernel<<<(1024 * 64) / 256, 256>>>(w1, w1g);
    conv_w2cat_kernel<<<(512 * 1088) / 256, 256>>>(w2, w2c);

    // --- mid = lrelu(grid @ w1grid.T + bias1): A = cat[:,0:64] ---
    launch_gemm(EP_LRELU_BIAS, cat, 1088, w1g, 64, mid, 1024, cat + 64, 1088,
                mid, 1024, bias1, NPIX, 1024, 64, 1, 1);

    // --- mem stack 1: halves of 1024 inside cat[:,64:1088] + fp32 mid ---
    // Final layer (s=7): fp32 outputs are dead (h2 reads only bf16 cat) -> WC=0.
    for (int s = 0; s < 8; s++) {
        int wc = (s < 7) ? 1 : 0;
        launch_gemm(EP_RES_OUT, cat + 64 + 512, 1088, wm1F + (size_t)s * 512 * 512, 512,
                    mid, 1024, cat + 64, 1088, mid, 1024, m1_bf + s * 512,
                    NPIX, 512, 512, 1, wc);
        launch_gemm(EP_RES_OUT, cat + 64, 1088, wm1G + (size_t)s * 512 * 512, 512,
                    mid + 512, 1024, cat + 64 + 512, 1088, mid + 512, 1024, m1_bg + s * 512,
                    NPIX, 512, 512, 1, wc);
    }

    // --- h2 = lrelu(cat @ w2cat.T + b2): single K=1088 GEMM ---
    launch_gemm(EP_LRELU_BIAS, cat, 1088, w2c, 1088, h2, 512, h2_bf, 512,
                h2, 512, b2, NPIX, 512, 1088, 1, 1);

    // --- mem stack 2: halves of 512 (256 each) ---
    // Final G (s=7): bf16 shadow of y2 is dead (head reads fp32) -> WBF=0.
    for (int s = 0; s < 8; s++) {
        launch_gemm(EP_RES_OUT, h2_bf + 256, 512, wm2F + (size_t)s * 256 * 256, 256,
                    h2, 512, h2_bf, 512, h2, 512, m2_bf + s * 256,
                    NPIX, 256, 256, 1, 1);
        int wbf = (s < 7) ? 1 : 0;
        launch_gemm(EP_RES_OUT, h2_bf, 512, wm2G + (size_t)s * 256 * 256, 256,
                    h2 + 256, 512, h2_bf + 256, 512, h2 + 256, 512, m2_bg + s * 256,
                    NPIX, 256, 256, wbf, 1);
    }

    // --- head (fp32 h2, float4 loads) ---
    head_kernel<<<NPIX / 8, 256>>>(h2, w3, b3, out);
}

// round 17
// speedup vs baseline: 1.8338x; 1.8338x over previous
#include <cuda_runtime.h>
#include <cuda_bf16.h>
#include <cstdint>
#include <math.h>

// ---------------------------------------------------------------------------
// Scratch
// ---------------------------------------------------------------------------
#define NPIX 65536
// concatenated bf16 activations: [grid(64, zero-padded) | mid(1024)]
__device__ __nv_bfloat16 g_cat[NPIX * 1088];
__device__ float         g_mid [NPIX * 1024];         // fp32 residual path
__device__ float         g_h2  [NPIX * 512];
__device__ __nv_bfloat16 g_h2_bf[NPIX * 512];
__device__ __nv_bfloat16 g_wm1F[8 * 512 * 512];
__device__ __nv_bfloat16 g_wm1G[8 * 512 * 512];
__device__ __nv_bfloat16 g_wm2F[8 * 256 * 256];
__device__ __nv_bfloat16 g_wm2G[8 * 256 * 256];
__device__ __nv_bfloat16 g_w1g_bf[1024 * 64];         // w1[:, :32] zero-padded
__device__ __nv_bfloat16 g_w2cat[512 * 1088];         // [w2grid(64pad) | w2mid(1024)]
__device__ float g_conv0[768 * 8 * 8];
__device__ float g_conv1[768 * 8 * 8];
__device__ float g_pad [1792 * 100];                  // zero-padded conv input (10x10)
__device__ float g_part[4 * 768 * 64];                // conv ic-chunk partials
__device__ float g_feat[2048];
__device__ float g_bias1[1024];

// ---------------------------------------------------------------------------
// Grid features -> bf16 into g_cat cols [0,64), stride 1088
// ---------------------------------------------------------------------------
__global__ void grid_kernel(__nv_bfloat16* __restrict__ cat) {
    int idx = blockIdx.x * blockDim.x + threadIdx.x;      // n*64 + c
    int n = idx >> 6, c = idx & 63;
    float val = 0.f;
    if (c < 32) {
        int i = n >> 8, j = n & 255;
        float r = (float)(((c & 1) ? j : i) - 128) * (float)(3.14159265358979323846 / 256.0);
        float s = exp2f(0.5f * (float)(c >> 1));
        val = sinf(r * s);
    }
    cat[(size_t)n * 1088 + c] = __float2bfloat16(val);
}

// ---------------------------------------------------------------------------
// Zero-pad [C,8,8] -> [C,10,10]
// ---------------------------------------------------------------------------
__global__ void pad_kernel(const float* __restrict__ in, float* __restrict__ out, int C) {
    int idx = blockIdx.x * blockDim.x + threadIdx.x;      // c*100 + iy*10 + ix
    if (idx >= C * 100) return;
    int c = idx / 100, r = idx % 100;
    int iy = r / 10, ix = r % 10;
    float v = 0.f;
    if (iy >= 1 && iy <= 8 && ix >= 1 && ix <= 8)
        v = in[c * 64 + (iy - 1) * 8 + (ix - 1)];
    out[idx] = v;
}

// ---------------------------------------------------------------------------
// Grouped 3x3 conv, branch-free taps (input pre-padded or valid-mode).
// grid(Cout, 4 ic-chunks), 512 threads, 8-way within-block ic split.
// ---------------------------------------------------------------------------
__global__ void conv_part_kernel(const float* __restrict__ in, const float* __restrict__ w,
                                 float* __restrict__ part,
                                 int Cout, int icpg, int ocpg,
                                 int rowStride, int chStride,
                                 int Hout, int Wout) {
    int oc = blockIdx.x;
    int chunk = blockIdx.y;                 // 0..3
    int grp = oc / ocpg;
    int csz  = icpg / 4;
    int base = chunk * csz;

    extern __shared__ float sm[];
    float* sw  = sm;                        // csz*9
    float* red = sm + csz * 9;              // 8*64
    for (int i = threadIdx.x; i < csz * 9; i += blockDim.x)
        sw[i] = w[(size_t)oc * icpg * 9 + base * 9 + i];
    __syncthreads();

    int icq = threadIdx.x >> 6;             // 0..7
    int px  = threadIdx.x & 63;
    float acc = 0.f;
    if (px < Hout * Wout) {
        int oy = px / Wout, ox = px % Wout;
        const float* inb = in + (size_t)(grp * icpg + base) * chStride
                              + oy * rowStride + ox;
        for (int ic = icq; ic < csz; ic += 8) {
            const float* ip = inb + (size_t)ic * chStride;
            const float* wp = sw + ic * 9;
            #pragma unroll
            for (int ky = 0; ky < 3; ky++)
                #pragma unroll
                for (int kx = 0; kx < 3; kx++)
                    acc = fmaf(ip[ky * rowStride + kx], wp[ky * 3 + kx], acc);
        }
    }
    red[icq * 64 + px] = acc;
    __syncthreads();
    if (icq == 0 && px < Hout * Wout) {
        float v = red[px];
        #pragma unroll
        for (int q = 1; q < 8; q++) v += red[q * 64 + px];
        part[((size_t)chunk * Cout + oc) * 64 + px] = v;
    }
}

// Reduce 4 chunk partials + bias + leaky_relu -> out[oc*HW + px]
__global__ void conv_reduce_kernel(const float* __restrict__ part,
                                   const float* __restrict__ bias,
                                   float* __restrict__ out, int Cout, int HW) {
    int idx = blockIdx.x * blockDim.x + threadIdx.x;
    if (idx >= Cout * HW) return;
    int oc = idx / HW, px = idx % HW;
    float v = bias[oc];
    #pragma unroll
    for (int c = 0; c < 4; c++)
        v += part[((size_t)c * Cout + oc) * 64 + px];
    out[idx] = v > 0.f ? v : 0.01f * v;
}

__global__ void wnorm_kernel(const float* __restrict__ v, const float* __restrict__ g,
                             __nv_bfloat16* __restrict__ w, int K) {
    int row = blockIdx.x;
    const float* vr = v + (size_t)row * K;
    float s = 0.f;
    for (int k = threadIdx.x; k < K; k += blockDim.x) { float x = vr[k]; s = fmaf(x, x, s); }
    __shared__ float red[128];
    red[threadIdx.x] = s;
    __syncthreads();
    for (int o = 64; o; o >>= 1) {
        if (threadIdx.x < o) red[threadIdx.x] += red[threadIdx.x + o];
        __syncthreads();
    }
    float scale = g[row] / sqrtf(red[0]);
    for (int k = threadIdx.x; k < K; k += blockDim.x)
        w[(size_t)row * K + k] = __float2bfloat16(vr[k] * scale);
}

__global__ void conv_w1g_kernel(const float* __restrict__ w1, __nv_bfloat16* __restrict__ o) {
    int idx = blockIdx.x * blockDim.x + threadIdx.x;   // 1024*64
    int j = idx >> 6, k = idx & 63;
    o[idx] = __float2bfloat16(k < 32 ? w1[(size_t)j * 2080 + k] : 0.f);
}
__global__ void conv_w2cat_kernel(const float* __restrict__ w2, __nv_bfloat16* __restrict__ o) {
    int idx = blockIdx.x * blockDim.x + threadIdx.x;   // 512*1088
    int j = idx / 1088, r = idx % 1088;
    float v;
    if (r < 32)       v = w2[(size_t)j * 1056 + r];
    else if (r < 64)  v = 0.f;
    else              v = w2[(size_t)j * 1056 + 32 + (r - 64)];
    o[idx] = __float2bfloat16(v);
}

__global__ void bias1_kernel(const float* __restrict__ feat, const float* __restrict__ w1,
                             const float* __restrict__ b1, float* __restrict__ out) {
    int j = blockIdx.x * 8 + (threadIdx.x >> 5);
    int lane = threadIdx.x & 31;
    const float* wr = w1 + (size_t)j * 2080 + 32;
    float s = 0.f;
    for (int k = lane; k < 2048; k += 32) s = fmaf(feat[k], wr[k], s);
    #pragma unroll
    for (int o = 16; o; o >>= 1) s += __shfl_down_sync(0xffffffffu, s, o);
    if (lane == 0) out[j] = b1[j] + s;
}

// head: fp32 h2 (accuracy margin), float4 loads
__global__ void head_kernel(const float* __restrict__ h2, const float* __restrict__ w3,
                            const float* __restrict__ b3, float* __restrict__ out) {
    __shared__ float sw[1536];
    for (int i = threadIdx.x; i < 1536; i += blockDim.x) sw[i] = w3[i];
    __syncthreads();
    int n = (blockIdx.x * blockDim.x + threadIdx.x) >> 5;
    int lane = threadIdx.x & 31;
    const float* hr = h2 + (size_t)n * 512;
    float d0 = 0.f, d1 = 0.f, d2 = 0.f;
    #pragma unroll
    for (int t = lane * 4; t < 512; t += 128) {
        float4 x = *reinterpret_cast<const float4*>(hr + t);
        d0 = fmaf(x.x, sw[t],        fmaf(x.y, sw[t + 1],        fmaf(x.z, sw[t + 2],        fmaf(x.w, sw[t + 3],        d0))));
        d1 = fmaf(x.x, sw[512 + t],  fmaf(x.y, sw[512 + t + 1],  fmaf(x.z, sw[512 + t + 2],  fmaf(x.w, sw[512 + t + 3],  d1))));
        d2 = fmaf(x.x, sw[1024 + t], fmaf(x.y, sw[1024 + t + 1], fmaf(x.z, sw[1024 + t + 2], fmaf(x.w, sw[1024 + t + 3], d2))));
    }
    #pragma unroll
    for (int o = 16; o; o >>= 1) {
        d0 += __shfl_down_sync(0xffffffffu, d0, o);
        d1 += __shfl_down_sync(0xffffffffu, d1, o);
        d2 += __shfl_down_sync(0xffffffffu, d2, o);
    }
    if (lane == 0) {
        out[n]          = 1.1f / (1.f + expf(-(d0 + b3[0]))) - 0.05f;
        out[65536 + n]  = 1.1f / (1.f + expf(-(d1 + b3[1]))) - 0.05f;
        out[131072 + n] = 1.1f / (1.f + expf(-(d2 + b3[2]))) - 0.05f;
    }
}

// ---------------------------------------------------------------------------
// bf16 GEMM: mma.sync.m16n8k16 + ldmatrix + cp.async.  (mainloop FROZEN)
// 128x128 CTA tile, 4 warps (2x2), warp tile 64x64, BK=64, 3 stages (96KB),
// 128 threads, __launch_bounds__(128,2) -> 2 CTAs/SM, fragment dbuf.
// Epilogue: PLAIN loads/stores (R14 path; .cs hints caused 1.8x regression),
// dead-store flags (WBF/WC) kept.
// ---------------------------------------------------------------------------
enum { EP_LRELU_BIAS = 1, EP_RES_OUT = 3 };

#define BM 128
#define BN 128
#define BKB 64
#define STAGES 3
#define OPB (BM * BKB * 2)        // 16 KB
#define STB (2 * OPB)             // 32 KB
#define GSMEM (STAGES * STB)      // 96 KB

__device__ __forceinline__ uint32_t smem_u32(const void* p) {
    uint32_t a;
    asm("{ .reg .u64 t; cvta.to.shared.u64 t, %1; cvt.u32.u64 %0, t; }" : "=r"(a) : "l"(p));
    return a;
}
__device__ __forceinline__ void cp_async16(uint32_t sa, const __nv_bfloat16* g) {
    asm volatile("cp.async.cg.shared.global [%0], [%1], 16;" :: "r"(sa), "l"(g));
}
__device__ __forceinline__ void ldsm4(uint32_t* r, uint32_t addr) {
    asm volatile("ldmatrix.sync.aligned.m8n8.x4.shared.b16 {%0,%1,%2,%3}, [%4];"
                 : "=r"(r[0]), "=r"(r[1]), "=r"(r[2]), "=r"(r[3]) : "r"(addr));
}
__device__ __forceinline__ void mma_bf16(float* c, const uint32_t* a, const uint32_t* b) {
    asm volatile(
        "mma.sync.aligned.m16n8k16.row.col.f32.bf16.bf16.f32 "
        "{%0,%1,%2,%3}, {%4,%5,%6,%7}, {%8,%9}, {%0,%1,%2,%3};"
        : "+f"(c[0]), "+f"(c[1]), "+f"(c[2]), "+f"(c[3])
        : "r"(a[0]), "r"(a[1]), "r"(a[2]), "r"(a[3]), "r"(b[0]), "r"(b[1]));
}
__device__ __forceinline__ uint32_t pack_bf16x2(float lo, float hi) {
    uint32_t u;
    asm("cvt.rn.bf16x2.f32 %0, %1, %2;" : "=r"(u) : "f"(hi), "f"(lo));
    return u;
}

template <int EP, int WBF, int WC>
__global__ __launch_bounds__(128, 2)
void gemm_bf(const __nv_bfloat16* __restrict__ A, int lda,
             const __nv_bfloat16* __restrict__ B, int ldb,
             float* __restrict__ C, int ldc,
             __nv_bfloat16* __restrict__ Cbf, int ldcbf,
             const float* __restrict__ Res, int ldres,
             const float* __restrict__ bias, int K) {
    extern __shared__ char smem[];
    uint32_t sbase = smem_u32(smem);

    int tid = threadIdx.x;
    int wid = tid >> 5, lane = tid & 31;
    int g = lane >> 2, tg = lane & 3;
    int wm = (wid >> 1) * 64;
    int wn = (wid & 1) * 64;

    long brow = blockIdx.y, bcol = blockIdx.x;
    const __nv_bfloat16* Ab = A + brow * BM * (long)lda;
    const __nv_bfloat16* Bb = B + bcol * BN * (long)ldb;
    C   += brow * BM * (long)ldc   + bcol * BN;
    if (WBF) Cbf += brow * BM * (long)ldcbf + bcol * BN;
    Res += brow * BM * (long)ldres + bcol * BN;
    const float* biasp = bias + bcol * BN;

    uint32_t aRow[4], aXor[4], bRow[4], bXor[4];
    uint32_t akb = (lane >> 4) * 16;
    uint32_t bkb = ((lane >> 3) & 1) * 16;
    #pragma unroll
    for (int s = 0; s < 4; s++) {
        uint32_t r = wm + s * 16 + (lane & 15);
        aRow[s] = r * 128;
        aXor[s] = (r & 7) << 4;
    }
    #pragma unroll
    for (int p = 0; p < 4; p++) {
        uint32_t r = wn + p * 16 + ((lane >> 4) << 3) + (lane & 7);
        bRow[p] = r * 128;
        bXor[p] = (r & 7) << 4;
    }

    float acc[4][8][4];
    #pragma unroll
    for (int s = 0; s < 4; s++)
        #pragma unroll
        for (int nt = 0; nt < 8; nt++)
            #pragma unroll
            for (int q = 0; q < 4; q++) acc[s][nt][q] = 0.f;

    int T = K / BKB;

    auto load_stage = [&](int u, int st) {
        const __nv_bfloat16* Ag = Ab + u * BKB;
        const __nv_bfloat16* Bg = Bb + u * BKB;
        uint32_t sA = sbase + st * STB;
        uint32_t sB = sA + OPB;
        #pragma unroll
        for (int j = 0; j < 8; j++) {
            int idx = tid + 128 * j;
            int r = idx >> 3, c = idx & 7;
            uint32_t sw = r * 128 + ((c * 16) ^ ((r & 7) << 4));
            cp_async16(sA + sw, Ag + (long)r * lda + c * 8);
            cp_async16(sB + sw, Bg + (long)r * ldb + c * 8);
        }
    };

    auto load_frags = [&](uint32_t sA, uint32_t sB, int kk,
                          uint32_t af[4][4], uint32_t bp[4][4]) {
        #pragma unroll
        for (int s = 0; s < 4; s++)
            ldsm4(af[s], sA + aRow[s] + (((kk * 32) + akb) ^ aXor[s]));
        #pragma unroll
        for (int p = 0; p < 4; p++)
            ldsm4(bp[p], sB + bRow[p] + (((kk * 32) + bkb) ^ bXor[p]));
    };

    #pragma unroll
    for (int p = 0; p < STAGES - 1; p++) {
        if (p < T) load_stage(p, p);
        asm volatile("cp.async.commit_group;");
    }

    uint32_t af[2][4][4], bp[2][4][4];

    for (int t = 0; t < T; t++) {
        asm volatile("cp.async.wait_group %0;" :: "n"(STAGES - 2));
        __syncthreads();
        int u = t + STAGES - 1;
        if (u < T) load_stage(u, u % STAGES);
        asm volatile("cp.async.commit_group;");

        uint32_t sA = sbase + (t % STAGES) * STB;
        uint32_t sB = sA + OPB;

        load_frags(sA, sB, 0, af[0], bp[0]);
        #pragma unroll
        for (int kk = 0; kk < 4; kk++) {
            int cur = kk & 1, nxt = cur ^ 1;
            if (kk < 3) load_frags(sA, sB, kk + 1, af[nxt], bp[nxt]);
            #pragma unroll
            for (int s = 0; s < 4; s++)
                #pragma unroll
                for (int p = 0; p < 4; p++) {
                    mma_bf16(acc[s][p * 2 + 0], af[cur][s], &bp[cur][p][0]);
                    mma_bf16(acc[s][p * 2 + 1], af[cur][s], &bp[cur][p][2]);
                }
        }
    }

    // epilogue (plain loads/stores; dead-store flags only)
    #pragma unroll
    for (int s = 0; s < 4; s++) {
        #pragma unroll
        for (int half = 0; half < 2; half++) {
            long row = wm + s * 16 + g + half * 8;
            #pragma unroll
            for (int nt = 0; nt < 8; nt++) {
                int col = wn + nt * 8 + tg * 2;
                float v0 = acc[s][nt][half * 2 + 0];
                float v1 = acc[s][nt][half * 2 + 1];
                if (EP == EP_LRELU_BIAS) {
                    v0 += biasp[col]; v1 += biasp[col + 1];
                    v0 = v0 > 0.f ? v0 : 0.01f * v0;
                    v1 = v1 > 0.f ? v1 : 0.01f * v1;
                } else {  // EP_RES_OUT
                    v0 += biasp[col]; v1 += biasp[col + 1];
                    v0 = v0 > 0.f ? v0 : 0.01f * v0;
                    v1 = v1 > 0.f ? v1 : 0.01f * v1;
                    float2 r = *reinterpret_cast<const float2*>(Res + row * ldres + col);
                    v0 += r.x; v1 += r.y;
                }
                if (WC) {
                    float2 o; o.x = v0; o.y = v1;
                    *reinterpret_cast<float2*>(C + row * ldc + col) = o;
                }
                if (WBF)
                    *reinterpret_cast<uint32_t*>(Cbf + row * ldcbf + col) = pack_bf16x2(v0, v1);
            }
        }
    }
}

static void launch_gemm(int ep, const __nv_bfloat16* A, int lda,
                        const __nv_bfloat16* B, int ldb,
                        float* C, int ldc, __nv_bfloat16* Cbf, int ldcbf,
                        const float* Res, int ldres,
                        const float* bias, int M, int N, int K,
                        int wbf, int wc) {
    dim3 grd(N / BN, M / BM);
    if (ep == EP_LRELU_BIAS) {
        cudaFuncSetAttribute(gemm_bf<EP_LRELU_BIAS, 1, 1>, cudaFuncAttributeMaxDynamicSharedMemorySize, GSMEM);
        gemm_bf<EP_LRELU_BIAS, 1, 1><<<grd, 128, GSMEM>>>(A, lda, B, ldb, C, ldc, Cbf, ldcbf, Res, ldres, bias, K);
    } else if (wbf && wc) {
        cudaFuncSetAttribute(gemm_bf<EP_RES_OUT, 1, 1>, cudaFuncAttributeMaxDynamicSharedMemorySize, GSMEM);
        gemm_bf<EP_RES_OUT, 1, 1><<<grd, 128, GSMEM>>>(A, lda, B, ldb, C, ldc, Cbf, ldcbf, Res, ldres, bias, K);
    } else if (wbf && !wc) {
        cudaFuncSetAttribute(gemm_bf<EP_RES_OUT, 1, 0>, cudaFuncAttributeMaxDynamicSharedMemorySize, GSMEM);
        gemm_bf<EP_RES_OUT, 1, 0><<<grd, 128, GSMEM>>>(A, lda, B, ldb, C, ldc, Cbf, ldcbf, Res, ldres, bias, K);
    } else {
        cudaFuncSetAttribute(gemm_bf<EP_RES_OUT, 0, 1>, cudaFuncAttributeMaxDynamicSharedMemorySize, GSMEM);
        gemm_bf<EP_RES_OUT, 0, 1><<<grd, 128, GSMEM>>>(A, lda, B, ldb, C, ldc, Cbf, ldcbf, Res, ldres, bias, K);
    }
}

// conv helper: optional pad + split conv + reduce (R11 configuration)
static void launch_conv(const float* in, const float* w, const float* bias, float* out,
                        float* part, float* padbuf,
                        int Cin, int Cout, int Hin, int Win,
                        int Hout, int Wout, int pad, int groups) {
    int icpg = Cin / groups;
    int ocpg = Cout / groups;
    int csz  = icpg / 4;
    int smem = (csz * 9 + 512) * 4;
    const float* src = in;
    int rowStride, chStride;
    if (pad == 1) {
        pad_kernel<<<(Cin * 100 + 255) / 256, 256>>>(in, padbuf, Cin);
        src = padbuf;
        rowStride = 10; chStride = 100;
    } else {
        rowStride = Win; chStride = Hin * Win;
    }
    conv_part_kernel<<<dim3(Cout, 4), 512, smem>>>(src, w, part, Cout, icpg, ocpg,
                                                   rowStride, chStride, Hout, Wout);
    int total = Cout * Hout * Wout;
    conv_reduce_kernel<<<(total + 255) / 256, 256>>>(part, bias, out, Cout, Hout * Wout);
}

// ---------------------------------------------------------------------------
// kernel_launch
// ---------------------------------------------------------------------------
extern "C" void kernel_launch(void* const* d_in, const int* in_sizes, int n_in,
                              void* d_out, int out_size) {
    const float* feature = (const float*)d_in[0];
    const float* cw1 = (const float*)d_in[1];  const float* cb1 = (const float*)d_in[2];
    const float* cw2 = (const float*)d_in[3];  const float* cb2 = (const float*)d_in[4];
    const float* cw3 = (const float*)d_in[5];  const float* cb3 = (const float*)d_in[6];
    const float* cw4 = (const float*)d_in[7];  const float* cb4 = (const float*)d_in[8];
    const float* cw5 = (const float*)d_in[9];  const float* cb5 = (const float*)d_in[10];
    const float* w1  = (const float*)d_in[11]; const float* b1  = (const float*)d_in[12];
    const float* m1_vf = (const float*)d_in[13]; const float* m1_gf = (const float*)d_in[14];
    const float* m1_bf = (const float*)d_in[15]; const float* m1_vg = (const float*)d_in[16];
    const float* m1_gg = (const float*)d_in[17]; const float* m1_bg = (const float*)d_in[18];
    const float* w2  = (const float*)d_in[19]; const float* b2  = (const float*)d_in[20];
    const float* m2_vf = (const float*)d_in[21]; const float* m2_gf = (const float*)d_in[22];
    const float* m2_bf = (const float*)d_in[23]; const float* m2_vg = (const float*)d_in[24];
    const float* m2_gg = (const float*)d_in[25]; const float* m2_bg = (const float*)d_in[26];
    const float* w3  = (const float*)d_in[27]; const float* b3  = (const float*)d_in[28];
    float* out = (float*)d_out;

    __nv_bfloat16 *cat, *h2_bf, *wm1F, *wm1G, *wm2F, *wm2G, *w1g, *w2c;
    float *mid, *h2, *conv0, *conv1, *padb, *part, *feat, *bias1;
    cudaGetSymbolAddress((void**)&cat,   g_cat);
    cudaGetSymbolAddress((void**)&mid,   g_mid);
    cudaGetSymbolAddress((void**)&h2,    g_h2);
    cudaGetSymbolAddress((void**)&h2_bf, g_h2_bf);
    cudaGetSymbolAddress((void**)&wm1F,  g_wm1F);
    cudaGetSymbolAddress((void**)&wm1G,  g_wm1G);
    cudaGetSymbolAddress((void**)&wm2F,  g_wm2F);
    cudaGetSymbolAddress((void**)&wm2G,  g_wm2G);
    cudaGetSymbolAddress((void**)&w1g,   g_w1g_bf);
    cudaGetSymbolAddress((void**)&w2c,   g_w2cat);
    cudaGetSymbolAddress((void**)&conv0, g_conv0);
    cudaGetSymbolAddress((void**)&conv1, g_conv1);
    cudaGetSymbolAddress((void**)&padb,  g_pad);
    cudaGetSymbolAddress((void**)&part,  g_part);
    cudaGetSymbolAddress((void**)&feat,  g_feat);
    cudaGetSymbolAddress((void**)&bias1, g_bias1);

    // --- positional grid features into cat[:, 0:64] ---
    grid_kernel<<<(NPIX * 64) / 256, 256>>>(cat);

    // --- conv stack ---
    launch_conv(feature, cw1, cb1, conv0, part, padb, 1792, 768, 8, 8, 8, 8, 1, 4);
    launch_conv(conv0,   cw2, cb2, conv1, part, padb, 768,  768, 8, 8, 8, 8, 1, 3);
    launch_conv(conv1,   cw3, cb3, conv0, part, padb, 768,  768, 8, 8, 8, 8, 1, 2);
    launch_conv(conv0,   cw4, cb4, conv1, part, padb, 768,  768, 8, 8, 6, 6, 0, 3);
    launch_conv(conv1,   cw5, cb5, feat,  part, padb, 768,  128, 6, 6, 4, 4, 0, 1);

    // --- fold feat @ w1[:,32:].T + b1 into a bias vector ---
    bias1_kernel<<<128, 256>>>(feat, w1, b1, bias1);

    // --- weight prep (bf16) ---
    wnorm_kernel<<<8 * 512, 128>>>(m1_vf, m1_gf, wm1F, 512);
    wnorm_kernel<<<8 * 512, 128>>>(m1_vg, m1_gg, wm1G, 512);
    wnorm_kernel<<<8 * 256, 128>>>(m2_vf, m2_gf, wm2F, 256);
    wnorm_kernel<<<8 * 256, 128>>>(m2_vg, m2_gg, wm2G, 256);
    conv_w1g_kernel<<<(1024 * 64) / 256, 256>>>(w1, w1g);
    conv_w2cat_kernel<<<(512 * 1088) / 256, 256>>>(w2, w2c);

    // --- mid = lrelu(grid @ w1grid.T + bias1): A = cat[:,0:64] ---
    launch_gemm(EP_LRELU_BIAS, cat, 1088, w1g, 64, mid, 1024, cat + 64, 1088,
                mid, 1024, bias1, NPIX, 1024, 64, 1, 1);

    // --- mem stack 1: halves of 1024 inside cat[:,64:1088] + fp32 mid ---
    // Final layer (s=7): fp32 outputs are dead (h2 reads only bf16 cat) -> WC=0.
    for (int s = 0; s < 8; s++) {
        int wc = (s < 7) ? 1 : 0;
        launch_gemm(EP_RES_OUT, cat + 64 + 512, 1088, wm1F + (size_t)s * 512 * 512, 512,
                    mid, 1024, cat + 64, 1088, mid, 1024, m1_bf + s * 512,
                    NPIX, 512, 512, 1, wc);
        launch_gemm(EP_RES_OUT, cat + 64, 1088, wm1G + (size_t)s * 512 * 512, 512,
                    mid + 512, 1024, cat + 64 + 512, 1088, mid + 512, 1024, m1_bg + s * 512,
                    NPIX, 512, 512, 1, wc);
    }

    // --- h2 = lrelu(cat @ w2cat.T + b2): single K=1088 GEMM ---
    launch_gemm(EP_LRELU_BIAS, cat, 1088, w2c, 1088, h2, 512, h2_bf, 512,
                h2, 512, b2, NPIX, 512, 1088, 1, 1);

    // --- mem stack 2: halves of 512 (256 each) ---
    // Final G (s=7): bf16 shadow of y2 is dead (head reads fp32) -> WBF=0.
    for (int s = 0; s < 8; s++) {
        launch_gemm(EP_RES_OUT, h2_bf + 256, 512, wm2F + (size_t)s * 256 * 256, 256,
                    h2, 512, h2_bf, 512, h2, 512, m2_bf + s * 256,
                    NPIX, 256, 256, 1, 1);
        int wbf = (s < 7) ? 1 : 0;
        launch_gemm(EP_RES_OUT, h2_bf, 512, wm2G + (size_t)s * 256 * 256, 256,
                    h2 + 256, 512, h2_bf + 256, 512, h2 + 256, 512, m2_bg + s * 256,
                    NPIX, 256, 256, wbf, 1);
    }

    // --- head (fp32 h2, float4 loads) ---
    head_kernel<<<NPIX / 8, 256>>>(h2, w3, b3, out);
}